// round 7
// baseline (speedup 1.0000x reference)
#include <cuda_runtime.h>
#include <cuda_bf16.h>
#include <cstdint>
#include <math.h>

// ---------------- problem constants ----------------
#define NN    100000
#define EE    400000
#define ETOT  500000   // EE + NN self loops
#define GG    4000
#define F_IN  32
#define HID   128
#define W3    384
#define NC    10
#define NEG_SLOPE 0.2f

// ---------------- scratch (device globals; no allocations allowed) ----------------
__device__ float          g_bufA[NN * W3];
__device__ float          g_bufB[NN * W3];
__device__ float          g_Hf  [NN * W3];
__device__ __nv_bfloat16  g_Xhi [NN * W3];
__device__ __nv_bfloat16  g_Xlo [NN * W3];
__device__ __nv_bfloat16  g_Yhi [NN * HID];
__device__ __nv_bfloat16  g_Ylo [NN * HID];
__device__ __nv_bfloat16  g_Whi [W3 * W3];
__device__ __nv_bfloat16  g_Wlo [W3 * W3];
__device__ float          g_es  [NN * 3];
__device__ float          g_ed  [NN * 3];
__device__ float          g_p   [ETOT * 3];   // normalized alpha (CSR order)
__device__ int            g_deg [NN];
__device__ int            g_off [NN];
__device__ int            g_cur [NN];
__device__ int            g_incl[NN];
__device__ int            g_bsum[128];
__device__ int            g_csr [ETOT];
__device__ float          g_pool[GG * W3];
__device__ float          g_cnt [GG];
__device__ float          g_g2  [GG * HID];
__device__ float          g_bnsum[W3];
__device__ float          g_bnsq [W3];
__device__ float          g_scale[W3];
__device__ float          g_shift[W3];

// ---------------- helpers ----------------
__device__ __forceinline__ uint32_t smem_u32(const void* p) {
    uint32_t a;
    asm("{ .reg .u64 t; cvta.to.shared.u64 t, %1; cvt.u32.u64 %0, t; }" : "=r"(a) : "l"(p));
    return a;
}
__device__ __forceinline__ void ldsm_x4(uint32_t* r, uint32_t addr) {
    asm volatile("ldmatrix.sync.aligned.m8n8.x4.shared.b16 {%0,%1,%2,%3}, [%4];"
                 : "=r"(r[0]), "=r"(r[1]), "=r"(r[2]), "=r"(r[3]) : "r"(addr));
}
__device__ __forceinline__ void mma16816(float* c, const uint32_t* a, uint32_t b0, uint32_t b1) {
    asm volatile(
        "mma.sync.aligned.m16n8k16.row.col.f32.bf16.bf16.f32 "
        "{%0,%1,%2,%3}, {%4,%5,%6,%7}, {%8,%9}, {%0,%1,%2,%3};"
        : "+f"(c[0]), "+f"(c[1]), "+f"(c[2]), "+f"(c[3])
        : "r"(a[0]), "r"(a[1]), "r"(a[2]), "r"(a[3]), "r"(b0), "r"(b1));
}
__device__ __forceinline__ void cp16(uint32_t smem, const void* g) {
    asm volatile("cp.async.cg.shared.global [%0], [%1], 16;" :: "r"(smem), "l"(g));
}
#define CP_COMMIT() asm volatile("cp.async.commit_group;" ::: "memory")
#define CP_WAIT(n)  asm volatile("cp.async.wait_group %0;" :: "n"(n) : "memory")

// ---------------- generic utility kernels ----------------
__global__ void zero_f(float* p, int n) {
    int i = blockIdx.x * blockDim.x + threadIdx.x;
    if (i < n) p[i] = 0.f;
}
__global__ void zero_f2(float* p1, float* p2, int n) {
    int i = blockIdx.x * blockDim.x + threadIdx.x;
    if (i < n) { p1[i] = 0.f; p2[i] = 0.f; }
}
__global__ void zero_i(int* p, int n) {
    int i = blockIdx.x * blockDim.x + threadIdx.x;
    if (i < n) p[i] = 0;
}

// transpose W[K,N] -> Wt[N,K] as bf16 hi/lo
__global__ void wsplit(const float* __restrict__ W, __nv_bfloat16* __restrict__ hi,
                       __nv_bfloat16* __restrict__ lo, int K, int N) {
    int i = blockIdx.x * blockDim.x + threadIdx.x;
    if (i >= K * N) return;
    int k = i / N, n = i % N;
    float v = W[i];
    __nv_bfloat16 h = __float2bfloat16(v);
    hi[n * K + k] = h;
    lo[n * K + k] = __float2bfloat16(v - __bfloat162float(h));
}

// ---------------- mma.sync bf16x2-split GEMM: C = A[M,K] @ Wt[N,K]^T ----------------
// CTA tile 512(M)x128(N), K chunk 32, cp.async double-buffered.
// 512 threads = 16 warps = 8(M) x 2(N), warp tile 64x64.
#define ASTR 40   // padded smem row stride (bf16 elems), chunk K=32
#define A_ELEMS (512 * ASTR)
#define B_ELEMS (128 * ASTR)
#define OFF_ALO (A_ELEMS * 2)            // bytes
#define OFF_BHI (2 * A_ELEMS * 2)
#define OFF_BLO (2 * A_ELEMS * 2 + B_ELEMS * 2)
#define BUF_BYTES (2 * (A_ELEMS + B_ELEMS) * 2)   // 102400
#define SMEM_MMA (2 * BUF_BYTES)                  // 204800

template <bool RELU, bool WF32, bool WB16, bool ESED>
__global__ void __launch_bounds__(512, 1) gemm_mma_kernel(
    const __nv_bfloat16* __restrict__ Ahi, const __nv_bfloat16* __restrict__ Alo,
    const __nv_bfloat16* __restrict__ Bhi, const __nv_bfloat16* __restrict__ Blo,
    const float* __restrict__ bias, float* __restrict__ C,
    __nv_bfloat16* __restrict__ Chi, __nv_bfloat16* __restrict__ Clo,
    const float* __restrict__ a_s, const float* __restrict__ a_d,
    float* __restrict__ es, float* __restrict__ ed,
    int M, int K, int N) {
    extern __shared__ __nv_bfloat16 sm[];
    const int tid = threadIdx.x;
    const int wid = tid >> 5, lane = tid & 31;
    const int tile0 = blockIdx.y * 512;   // M offset
    const int col0 = blockIdx.x * 128;    // N offset
    const int mbase = (wid & 7) * 64;     // warp M offset within tile
    const int nbase = (wid >> 3) * 64;    // warp N offset within tile
    const uint32_t base0 = smem_u32(sm);

    float acc[4][8][4];
#pragma unroll
    for (int i = 0; i < 4; i++)
#pragma unroll
        for (int j = 0; j < 8; j++)
#pragma unroll
            for (int r = 0; r < 4; r++) acc[i][j][r] = 0.f;

    const int lrow = (lane & 7) + 8 * ((lane >> 3) & 1);
    const int lcol = 8 * (lane >> 4);
    const int nchunks = K >> 5;

    auto stage = [&](int c, int b) {
        const uint32_t bb = base0 + b * BUF_BYTES;
        const int k0 = c << 5;
        // A: 512 rows x 32 bf16 -> 4 x 16B per row; 2048 cp per matrix
#pragma unroll
        for (int it = 0; it < 4; it++) {
            int f = tid + it * 512;
            int r = f >> 2, q = (f & 3) * 8;
            int rg = min(tile0 + r, M - 1);
            uint32_t sw = (uint32_t)(r * ASTR + q) * 2;
            cp16(bb + sw,           Ahi + (size_t)rg * K + k0 + q);
            cp16(bb + OFF_ALO + sw, Alo + (size_t)rg * K + k0 + q);
        }
        // B: 128 rows x 32 bf16 -> 512 cp per matrix
        {
            int f = tid;
            int r = f >> 2, q = (f & 3) * 8;
            int nr = col0 + r;
            uint32_t sw = (uint32_t)(r * ASTR + q) * 2;
            cp16(bb + OFF_BHI + sw, Bhi + (size_t)nr * K + k0 + q);
            cp16(bb + OFF_BLO + sw, Blo + (size_t)nr * K + k0 + q);
        }
    };

    stage(0, 0); CP_COMMIT();

    for (int c = 0; c < nchunks; c++) {
        if (c + 1 < nchunks) {
            stage(c + 1, (c + 1) & 1); CP_COMMIT(); CP_WAIT(1);
        } else {
            CP_WAIT(0);
        }
        __syncthreads();

        const uint32_t bb = base0 + (c & 1) * BUF_BYTES;
        const uint32_t uAh = bb, uAl = bb + OFF_ALO;
        const uint32_t uBh = bb + OFF_BHI, uBl = bb + OFF_BLO;

#pragma unroll
        for (int ks = 0; ks < 2; ks++) {
            const int kk = ks * 16;
            uint32_t ah[4][4], al[4][4], bh[4][4], bl[4][4];
#pragma unroll
            for (int am = 0; am < 4; am++) {
                uint32_t off = (uint32_t)(((mbase + am * 16 + lrow) * ASTR + kk + lcol) * 2);
                ldsm_x4(ah[am], uAh + off);
                ldsm_x4(al[am], uAl + off);
            }
#pragma unroll
            for (int bb2 = 0; bb2 < 4; bb2++) {
                uint32_t off = (uint32_t)(((nbase + bb2 * 16 + lrow) * ASTR + kk + lcol) * 2);
                ldsm_x4(bh[bb2], uBh + off);
                ldsm_x4(bl[bb2], uBl + off);
            }
#pragma unroll
            for (int am = 0; am < 4; am++) {
#pragma unroll
                for (int bb2 = 0; bb2 < 4; bb2++) {
                    mma16816(acc[am][bb2 * 2 + 0], ah[am], bh[bb2][0], bh[bb2][2]);
                    mma16816(acc[am][bb2 * 2 + 1], ah[am], bh[bb2][1], bh[bb2][3]);
                    mma16816(acc[am][bb2 * 2 + 0], ah[am], bl[bb2][0], bl[bb2][2]);
                    mma16816(acc[am][bb2 * 2 + 1], ah[am], bl[bb2][1], bl[bb2][3]);
                    mma16816(acc[am][bb2 * 2 + 0], al[am], bh[bb2][0], bh[bb2][2]);
                    mma16816(acc[am][bb2 * 2 + 1], al[am], bh[bb2][1], bh[bb2][3]);
                }
            }
        }
        __syncthreads();
    }

    // preload attention vector slices (head = blockIdx.x when N == W3)
    float asv[8][2], adv[8][2];
    if (ESED) {
        const int head = blockIdx.x;
#pragma unroll
        for (int an = 0; an < 8; an++) {
            int cl = nbase + an * 8 + (lane & 3) * 2;
#pragma unroll
            for (int j = 0; j < 2; j++) {
                asv[an][j] = a_s[head * HID + cl + j];
                adv[an][j] = a_d[head * HID + cl + j];
            }
        }
    }

    // mbase warp M span is 64 rows -> am atoms of 16
#pragma unroll
    for (int am = 0; am < 4; am++) {
#pragma unroll
        for (int h = 0; h < 2; h++) {
            int row = tile0 + mbase + am * 16 + (lane >> 2) + h * 8;
            bool ok = row < M;
            float se_s = 0.f, se_d = 0.f;
#pragma unroll
            for (int an = 0; an < 8; an++) {
                int col = col0 + nbase + an * 8 + (lane & 3) * 2;
                float v0 = acc[am][an][h * 2 + 0] + (bias ? bias[col + 0] : 0.f);
                float v1 = acc[am][an][h * 2 + 1] + (bias ? bias[col + 1] : 0.f);
                if (RELU) { v0 = fmaxf(v0, 0.f); v1 = fmaxf(v1, 0.f); }
                if (ok) {
                    if (WF32) {
                        float2 f2; f2.x = v0; f2.y = v1;
                        *(float2*)(C + (size_t)row * N + col) = f2;
                    }
                    if (WB16) {
                        __nv_bfloat16 h0 = __float2bfloat16(v0);
                        __nv_bfloat16 h1 = __float2bfloat16(v1);
                        __nv_bfloat162 hh; hh.x = h0; hh.y = h1;
                        __nv_bfloat162 ll;
                        ll.x = __float2bfloat16(v0 - __bfloat162float(h0));
                        ll.y = __float2bfloat16(v1 - __bfloat162float(h1));
                        *(__nv_bfloat162*)(Chi + (size_t)row * N + col) = hh;
                        *(__nv_bfloat162*)(Clo + (size_t)row * N + col) = ll;
                    }
                }
                if (ESED) {
                    se_s = fmaf(v0, asv[an][0], fmaf(v1, asv[an][1], se_s));
                    se_d = fmaf(v0, adv[an][0], fmaf(v1, adv[an][1], se_d));
                }
            }
            if (ESED) {
                se_s += __shfl_xor_sync(0xffffffffu, se_s, 1);
                se_s += __shfl_xor_sync(0xffffffffu, se_s, 2);
                se_d += __shfl_xor_sync(0xffffffffu, se_d, 1);
                se_d += __shfl_xor_sync(0xffffffffu, se_d, 2);
                if (ok && (lane & 3) == 0) {
                    atomicAdd(&es[row * 3 + blockIdx.x], se_s);
                    atomicAdd(&ed[row * 3 + blockIdx.x], se_d);
                }
            }
        }
    }
}

// ---------------- fp32 GEMM (lin1 w/ bf16 split out, lin3) ----------------
template <bool RELU, bool WB16>
__global__ void gemm_kernel(const float* __restrict__ A, const float* __restrict__ B,
                            const float* __restrict__ bias, float* __restrict__ C,
                            __nv_bfloat16* __restrict__ Chi, __nv_bfloat16* __restrict__ Clo,
                            int M, int K, int Nc) {
    __shared__ float As[8][128];
    __shared__ float Bs[8][128];
    const int tid = threadIdx.x;
    const int tx = tid & 15, ty = tid >> 4;
    const int row0 = blockIdx.y * 128;
    const int col0 = blockIdx.x * 128;
    float acc[8][8];
#pragma unroll
    for (int i = 0; i < 8; i++)
#pragma unroll
        for (int j = 0; j < 8; j++) acc[i][j] = 0.f;

    for (int k0 = 0; k0 < K; k0 += 8) {
#pragma unroll
        for (int i = 0; i < 4; i++) {
            int flat = tid + i * 256;
            int r = flat >> 3, kk = flat & 7;
            int gr = row0 + r;
            As[kk][r] = (gr < M) ? A[(size_t)gr * K + k0 + kk] : 0.f;
        }
#pragma unroll
        for (int i = 0; i < 4; i++) {
            int flat = tid + i * 256;
            int kk = flat >> 7, cc = flat & 127;
            Bs[kk][cc] = B[(size_t)(k0 + kk) * Nc + col0 + cc];
        }
        __syncthreads();
#pragma unroll
        for (int kk = 0; kk < 8; kk++) {
            float a[8], b[8];
#pragma unroll
            for (int i = 0; i < 8; i++) a[i] = As[kk][ty + 16 * i];
#pragma unroll
            for (int j = 0; j < 8; j++) b[j] = Bs[kk][tx + 16 * j];
#pragma unroll
            for (int i = 0; i < 8; i++)
#pragma unroll
                for (int j = 0; j < 8; j++) acc[i][j] = fmaf(a[i], b[j], acc[i][j]);
        }
        __syncthreads();
    }
#pragma unroll
    for (int i = 0; i < 8; i++) {
        int gr = row0 + ty + 16 * i;
        if (gr >= M) continue;
#pragma unroll
        for (int j = 0; j < 8; j++) {
            int gc = col0 + tx + 16 * j;
            float v = acc[i][j] + (bias ? bias[gc] : 0.f);
            if (RELU) v = fmaxf(v, 0.f);
            if (WB16) {
                __nv_bfloat16 h = __float2bfloat16(v);
                Chi[(size_t)gr * Nc + gc] = h;
                Clo[(size_t)gr * Nc + gc] = __float2bfloat16(v - __bfloat162float(h));
            } else {
                C[(size_t)gr * Nc + gc] = v;
            }
        }
    }
}

// ---------------- CSR build ----------------
__global__ void count_deg(const int* __restrict__ ei, int* __restrict__ deg) {
    int e = blockIdx.x * blockDim.x + threadIdx.x;
    if (e >= ETOT) return;
    int d = (e < EE) ? ei[EE + e] : (e - EE);
    atomicAdd(&deg[d], 1);
}
__global__ void scan_block(const int* __restrict__ deg, int* __restrict__ incl, int* __restrict__ bsum) {
    __shared__ int sh[1024];
    int i = blockIdx.x * 1024 + threadIdx.x;
    sh[threadIdx.x] = (i < NN) ? deg[i] : 0;
    __syncthreads();
#pragma unroll
    for (int o = 1; o < 1024; o <<= 1) {
        int t = (threadIdx.x >= o) ? sh[threadIdx.x - o] : 0;
        __syncthreads();
        sh[threadIdx.x] += t;
        __syncthreads();
    }
    if (i < NN) incl[i] = sh[threadIdx.x];
    if (threadIdx.x == 1023) bsum[blockIdx.x] = sh[1023];
}
__global__ void scan_bsum(int* bsum, int nb) {
    if (blockIdx.x == 0 && threadIdx.x == 0) {
        int run = 0;
        for (int i = 0; i < nb; i++) { int v = bsum[i]; bsum[i] = run; run += v; }
    }
}
__global__ void scan_final(const int* __restrict__ deg, const int* __restrict__ incl,
                           const int* __restrict__ bsum, int* __restrict__ off,
                           int* __restrict__ cur) {
    int i = blockIdx.x * 1024 + threadIdx.x;
    if (i < NN) {
        int o = incl[i] - deg[i] + bsum[blockIdx.x];
        off[i] = o;
        cur[i] = o;
    }
}
__global__ void csr_fill(const int* __restrict__ ei, int* __restrict__ cur, int* __restrict__ csr) {
    int e = blockIdx.x * blockDim.x + threadIdx.x;
    if (e >= ETOT) return;
    int d = (e < EE) ? ei[EE + e] : (e - EE);
    int pos = atomicAdd(&cur[d], 1);
    csr[pos] = e;
}

// ---------------- CSR-ordered attention: per-node softmax, no atomics ----------------
__global__ void attn_csr(const int* __restrict__ ei, const int* __restrict__ csr,
                         const int* __restrict__ off, const int* __restrict__ deg,
                         const float* __restrict__ es, const float* __restrict__ ed,
                         float* __restrict__ alpha) {
    int n = blockIdx.x * blockDim.x + threadIdx.x;
    if (n >= NN) return;
    int beg = off[n], end = beg + deg[n];
    float d0 = ed[n * 3 + 0], d1 = ed[n * 3 + 1], d2 = ed[n * 3 + 2];
    float m0 = -1e30f, m1 = -1e30f, m2 = -1e30f;
    for (int i = beg; i < end; i++) {
        int e = csr[i];
        int s = (e < EE) ? ei[e] : (e - EE);
        float v0 = es[s * 3 + 0] + d0; v0 = (v0 > 0.f) ? v0 : NEG_SLOPE * v0;
        float v1 = es[s * 3 + 1] + d1; v1 = (v1 > 0.f) ? v1 : NEG_SLOPE * v1;
        float v2 = es[s * 3 + 2] + d2; v2 = (v2 > 0.f) ? v2 : NEG_SLOPE * v2;
        m0 = fmaxf(m0, v0); m1 = fmaxf(m1, v1); m2 = fmaxf(m2, v2);
    }
    float s0 = 0.f, s1 = 0.f, s2 = 0.f;
    for (int i = beg; i < end; i++) {
        int e = csr[i];
        int s = (e < EE) ? ei[e] : (e - EE);
        float v0 = es[s * 3 + 0] + d0; v0 = (v0 > 0.f) ? v0 : NEG_SLOPE * v0;
        float v1 = es[s * 3 + 1] + d1; v1 = (v1 > 0.f) ? v1 : NEG_SLOPE * v1;
        float v2 = es[s * 3 + 2] + d2; v2 = (v2 > 0.f) ? v2 : NEG_SLOPE * v2;
        float p0 = __expf(v0 - m0), p1 = __expf(v1 - m1), p2 = __expf(v2 - m2);
        alpha[i * 3 + 0] = p0; alpha[i * 3 + 1] = p1; alpha[i * 3 + 2] = p2;
        s0 += p0; s1 += p1; s2 += p2;
    }
    float i0 = 1.f / s0, i1 = 1.f / s1, i2 = 1.f / s2;
    for (int i = beg; i < end; i++) {
        alpha[i * 3 + 0] *= i0;
        alpha[i * 3 + 1] *= i1;
        alpha[i * 3 + 2] *= i2;
    }
}

// ---------------- aggregation with fused BN stats ----------------
#define NPB 8
__global__ void __launch_bounds__(W3) aggregate(
    const float* __restrict__ Hf, const int* __restrict__ ei,
    const int* __restrict__ csr, const int* __restrict__ off,
    const int* __restrict__ deg, const float* __restrict__ alpha,
    const float* __restrict__ bias,
    float* __restrict__ out, float* __restrict__ bnsum, float* __restrict__ bnsq) {
    const int c = threadIdx.x;            // 0..383
    const int h = c >> 7;                 // head
    const int n0 = blockIdx.x * NPB;
    const float bcol = bias[c];
    float s = 0.f, q = 0.f;
#pragma unroll 1
    for (int k = 0; k < NPB; k++) {
        int n = n0 + k;
        float a = 0.f;
        int beg = off[n], end = beg + deg[n];
        for (int i = beg; i < end; i++) {
            int e = csr[i];
            int sidx = (e < EE) ? ei[e] : (e - EE);
            a = fmaf(alpha[i * 3 + h], Hf[(size_t)sidx * W3 + c], a);
        }
        float v = a + bcol;
        out[(size_t)n * W3 + c] = v;
        s += v;
        q = fmaf(v, v, q);
    }
    atomicAdd(&bnsum[c], s);
    atomicAdd(&bnsq[c], q);
}

// ---------------- batch norm ----------------
__global__ void bn_coef(const float* __restrict__ sum, const float* __restrict__ sq,
                        const float* __restrict__ gamma, const float* __restrict__ beta,
                        float* __restrict__ scale, float* __restrict__ shift) {
    int c = threadIdx.x;
    float mu = sum[c] * (1.f / NN);
    float var = sq[c] * (1.f / NN) - mu * mu;
    float sc = rsqrtf(var + 1e-5f) * gamma[c];
    scale[c] = sc;
    shift[c] = beta[c] - mu * sc;
}
__global__ void bn_apply_b16(const float* __restrict__ x, const float* __restrict__ scale,
                             const float* __restrict__ shift,
                             __nv_bfloat16* __restrict__ hi, __nv_bfloat16* __restrict__ lo) {
    int c = threadIdx.x;
    int n = blockIdx.x;
    size_t i = (size_t)n * W3 + c;
    float v = fmaf(x[i], scale[c], shift[c]);
    __nv_bfloat16 h = __float2bfloat16(v);
    hi[i] = h;
    lo[i] = __float2bfloat16(v - __bfloat162float(h));
}

// ---------------- pooling + head ----------------
__global__ void pool_add(const float* __restrict__ x, const int* __restrict__ batch,
                         float* __restrict__ pool) {
    int n = blockIdx.x;
    int c = threadIdx.x;
    atomicAdd(&pool[(size_t)batch[n] * W3 + c], x[(size_t)n * W3 + c]);
}
__global__ void cnt_add(const int* __restrict__ batch, float* __restrict__ cnt) {
    int n = blockIdx.x * blockDim.x + threadIdx.x;
    if (n < NN) atomicAdd(&cnt[batch[n]], 1.f);
}
// mean + layer-3 BN affine folded in (mean(BN(x)) == BN(mean(x)))
__global__ void pool_div_bn(float* __restrict__ pool, const float* __restrict__ cnt,
                            const float* __restrict__ scale, const float* __restrict__ shift) {
    int g = blockIdx.x;
    int c = threadIdx.x;
    float m = pool[(size_t)g * W3 + c] / fmaxf(cnt[g], 1.f);
    pool[(size_t)g * W3 + c] = fmaf(m, scale[c], shift[c]);
}
__global__ void head_kernel(const float* __restrict__ g2, const float* __restrict__ w4,
                            const float* __restrict__ b4, float* __restrict__ out) {
    int g = blockIdx.x * blockDim.x + threadIdx.x;
    if (g >= GG) return;
    float acc[NC];
#pragma unroll
    for (int j = 0; j < NC; j++) acc[j] = b4[j];
    for (int c = 0; c < HID; c++) {
        float v = g2[(size_t)g * HID + c];
#pragma unroll
        for (int j = 0; j < NC; j++) acc[j] = fmaf(v, w4[c * NC + j], acc[j]);
    }
    float mx = acc[0];
#pragma unroll
    for (int j = 1; j < NC; j++) mx = fmaxf(mx, acc[j]);
    float se = 0.f;
#pragma unroll
    for (int j = 0; j < NC; j++) se += expf(acc[j] - mx);
    float l = logf(se) + mx;
#pragma unroll
    for (int j = 0; j < NC; j++) out[(size_t)g * NC + j] = acc[j] - l;
}

extern "C" void kernel_launch(void* const* d_in, const int* in_sizes, int n_in,
                              void* d_out, int out_size) {
    const float* x      = (const float*)d_in[0];
    const int*   ei     = (const int*)d_in[1];
    const int*   batch  = (const int*)d_in[2];
    const float* lin1_w = (const float*)d_in[3];
    const float* lin1_b = (const float*)d_in[4];
    const float* lin2_w = (const float*)d_in[5];
    const float* lin2_b = (const float*)d_in[6];
    const float* w0     = (const float*)d_in[7];
    const float* as0    = (const float*)d_in[8];
    const float* ad0    = (const float*)d_in[9];
    const float* b0     = (const float*)d_in[10];
    const float* wl     = (const float*)d_in[11];
    const float* asl    = (const float*)d_in[12];
    const float* adl    = (const float*)d_in[13];
    const float* bl     = (const float*)d_in[14];
    const float* gamma  = (const float*)d_in[15];
    const float* beta   = (const float*)d_in[16];
    const float* lin3_w = (const float*)d_in[17];
    const float* lin3_b = (const float*)d_in[18];
    const float* lin4_w = (const float*)d_in[19];
    const float* lin4_b = (const float*)d_in[20];
    float* out = (float*)d_out;

    float *pA, *pB, *pH, *pes, *ped, *palpha, *ppool, *pcnt, *pg2;
    float *pbnsum, *pbnsq, *pscale, *pshift;
    int *pdeg, *poff, *pcur, *pincl, *pbs, *pcsr;
    __nv_bfloat16 *pXhi, *pXlo, *pYhi, *pYlo, *pWhi, *pWlo;
    cudaGetSymbolAddress((void**)&pA, g_bufA);
    cudaGetSymbolAddress((void**)&pB, g_bufB);
    cudaGetSymbolAddress((void**)&pH, g_Hf);
    cudaGetSymbolAddress((void**)&pXhi, g_Xhi);
    cudaGetSymbolAddress((void**)&pXlo, g_Xlo);
    cudaGetSymbolAddress((void**)&pYhi, g_Yhi);
    cudaGetSymbolAddress((void**)&pYlo, g_Ylo);
    cudaGetSymbolAddress((void**)&pWhi, g_Whi);
    cudaGetSymbolAddress((void**)&pWlo, g_Wlo);
    cudaGetSymbolAddress((void**)&pes, g_es);
    cudaGetSymbolAddress((void**)&ped, g_ed);
    cudaGetSymbolAddress((void**)&palpha, g_p);
    cudaGetSymbolAddress((void**)&pdeg, g_deg);
    cudaGetSymbolAddress((void**)&poff, g_off);
    cudaGetSymbolAddress((void**)&pcur, g_cur);
    cudaGetSymbolAddress((void**)&pincl, g_incl);
    cudaGetSymbolAddress((void**)&pbs, g_bsum);
    cudaGetSymbolAddress((void**)&pcsr, g_csr);
    cudaGetSymbolAddress((void**)&ppool, g_pool);
    cudaGetSymbolAddress((void**)&pcnt, g_cnt);
    cudaGetSymbolAddress((void**)&pg2, g_g2);
    cudaGetSymbolAddress((void**)&pbnsum, g_bnsum);
    cudaGetSymbolAddress((void**)&pbnsq, g_bnsq);
    cudaGetSymbolAddress((void**)&pscale, g_scale);
    cudaGetSymbolAddress((void**)&pshift, g_shift);

    cudaFuncSetAttribute(gemm_mma_kernel<true, false, true, false>,
                         cudaFuncAttributeMaxDynamicSharedMemorySize, SMEM_MMA);
    cudaFuncSetAttribute(gemm_mma_kernel<false, true, false, true>,
                         cudaFuncAttributeMaxDynamicSharedMemorySize, SMEM_MMA);

    const int MB128 = (NN + 127) / 128;   // 782
    const int MB512 = (NN + 511) / 512;   // 196

    // ---- MLP stem ----
    {   // lin1: fp32 gemm, emit bf16 hi/lo directly (relu applied)
        dim3 grid(2, MB128);
        gemm_kernel<true, true><<<grid, 256>>>(x, lin1_w, lin1_b, nullptr,
                                               pXhi, pXlo, NN, F_IN, 2 * HID);
    }
    wsplit<<<(256 * 128 + 255) / 256, 256>>>(lin2_w, pWhi, pWlo, 256, 128);
    {   // lin2: tensor gemm, relu, emit bf16 hi/lo into Y
        dim3 grid(1, MB512);
        gemm_mma_kernel<true, false, true, false><<<grid, 512, SMEM_MMA>>>(
            pXhi, pXlo, pWhi, pWlo, lin2_b, nullptr, pYhi, pYlo,
            nullptr, nullptr, nullptr, nullptr, NN, 256, 128);
    }

    // ---- CSR build (by dst) ----
    zero_i<<<(NN + 255) / 256, 256>>>(pdeg, NN);
    count_deg<<<(ETOT + 255) / 256, 256>>>(ei, pdeg);
    const int NB = (NN + 1023) / 1024;
    scan_block<<<NB, 1024>>>(pdeg, pincl, pbs);
    scan_bsum<<<1, 32>>>(pbs, NB);
    scan_final<<<NB, 1024>>>(pdeg, pincl, pbs, poff, pcur);
    csr_fill<<<(ETOT + 255) / 256, 256>>>(ei, pcur, pcsr);

    // ---- GAT layers ----
    float* Xin = pA;
    float* Xout = pB;
    for (int l = 0; l < 4; l++) {
        const float* W    = (l == 0) ? w0  : wl  + (size_t)(l - 1) * W3 * W3;
        const float* a_s  = (l == 0) ? as0 : asl + (l - 1) * 3 * HID;
        const float* a_d  = (l == 0) ? ad0 : adl + (l - 1) * 3 * HID;
        const float* bias = (l == 0) ? b0  : bl  + (l - 1) * W3;
        const int K       = (l == 0) ? HID : W3;
        const __nv_bfloat16* Ah = (l == 0) ? pYhi : pXhi;
        const __nv_bfloat16* Al = (l == 0) ? pYlo : pXlo;

        wsplit<<<(K * W3 + 255) / 256, 256>>>(W, pWhi, pWlo, K, W3);
        zero_f2<<<(NN * 3 + 255) / 256, 256>>>(pes, ped, NN * 3);
        {
            dim3 grid(3, MB512);
            gemm_mma_kernel<false, true, false, true><<<grid, 512, SMEM_MMA>>>(
                Ah, Al, pWhi, pWlo, nullptr, pH, nullptr, nullptr,
                a_s, a_d, pes, ped, NN, K, W3);
        }

        attn_csr<<<(NN + 255) / 256, 256>>>(ei, pcsr, poff, pdeg, pes, ped, palpha);

        zero_f2<<<3, 256>>>(pbnsum, pbnsq, W3);
        aggregate<<<NN / NPB, W3>>>(pH, ei, pcsr, poff, pdeg, palpha, bias,
                                    Xout, pbnsum, pbnsq);
        bn_coef<<<1, W3>>>(pbnsum, pbnsq, gamma + l * W3, beta + l * W3, pscale, pshift);
        if (l < 3)
            bn_apply_b16<<<NN, W3>>>(Xout, pscale, pshift, pXhi, pXlo);
        // layer 3: BN affine folded into pool_div_bn

        float* t = Xin; Xin = Xout; Xout = t;
    }

    // ---- global mean pool (+ layer-3 BN affine) ----
    zero_f<<<(GG * W3 + 255) / 256, 256>>>(ppool, GG * W3);
    zero_f<<<(GG + 255) / 256, 256>>>(pcnt, GG);
    pool_add<<<NN, W3>>>(Xin, batch, ppool);
    cnt_add<<<(NN + 255) / 256, 256>>>(batch, pcnt);
    pool_div_bn<<<GG, W3>>>(ppool, pcnt, pscale, pshift);

    // ---- head ----
    {
        dim3 grid(1, (GG + 127) / 128);
        gemm_kernel<true, false><<<grid, 256>>>(ppool, lin3_w, lin3_b, pg2,
                                                nullptr, nullptr, GG, W3, HID);
    }
    head_kernel<<<(GG + 127) / 128, 128>>>(pg2, lin4_w, lin4_b, out);
}

// round 10
// speedup vs baseline: 1.3322x; 1.3322x over previous
#include <cuda_runtime.h>
#include <cuda_bf16.h>
#include <cstdint>
#include <math.h>

// ---------------- problem constants ----------------
#define NN    100000
#define EE    400000
#define ETOT  500000   // EE + NN self loops
#define GG    4000
#define F_IN  32
#define HID   128
#define W3    384
#define NC    10
#define NEG_SLOPE 0.2f

// ---------------- scratch (device globals; no allocations allowed) ----------------
__device__ float          g_bufA[NN * W3];
__device__ float          g_bufB[NN * W3];
__device__ float          g_Hf  [NN * W3];
__device__ __nv_bfloat16  g_Xhi [NN * W3];
__device__ __nv_bfloat16  g_Xlo [NN * W3];
__device__ __nv_bfloat16  g_Yhi [NN * HID];
__device__ __nv_bfloat16  g_Ylo [NN * HID];
__device__ __nv_bfloat16  g_Whi [W3 * W3];
__device__ __nv_bfloat16  g_Wlo [W3 * W3];
__device__ float          g_es  [NN * 3];
__device__ float          g_ed  [NN * 3];
__device__ float          g_p   [ETOT * 3];   // logits -> exp -> normalized alpha (CSR order)
__device__ int            g_deg [NN];
__device__ int            g_off [NN];
__device__ int            g_cur [NN];
__device__ int            g_incl[NN];
__device__ int            g_bsum[128];
__device__ int            g_csr [ETOT];
__device__ float          g_pool[GG * W3];
__device__ float          g_cnt [GG];
__device__ float          g_g2  [GG * HID];
__device__ float          g_bnsum[W3];
__device__ float          g_bnsq [W3];
__device__ float          g_scale[W3];
__device__ float          g_shift[W3];

// ---------------- helpers ----------------
__device__ __forceinline__ uint32_t smem_u32(const void* p) {
    uint32_t a;
    asm("{ .reg .u64 t; cvta.to.shared.u64 t, %1; cvt.u32.u64 %0, t; }" : "=r"(a) : "l"(p));
    return a;
}
__device__ __forceinline__ void ldsm_x4(uint32_t* r, uint32_t addr) {
    asm volatile("ldmatrix.sync.aligned.m8n8.x4.shared.b16 {%0,%1,%2,%3}, [%4];"
                 : "=r"(r[0]), "=r"(r[1]), "=r"(r[2]), "=r"(r[3]) : "r"(addr));
}
__device__ __forceinline__ void mma16816(float* c, const uint32_t* a, uint32_t b0, uint32_t b1) {
    asm volatile(
        "mma.sync.aligned.m16n8k16.row.col.f32.bf16.bf16.f32 "
        "{%0,%1,%2,%3}, {%4,%5,%6,%7}, {%8,%9}, {%0,%1,%2,%3};"
        : "+f"(c[0]), "+f"(c[1]), "+f"(c[2]), "+f"(c[3])
        : "r"(a[0]), "r"(a[1]), "r"(a[2]), "r"(a[3]), "r"(b0), "r"(b1));
}
__device__ __forceinline__ void cp16(uint32_t smem, const void* g) {
    asm volatile("cp.async.cg.shared.global [%0], [%1], 16;" :: "r"(smem), "l"(g));
}
#define CP_COMMIT() asm volatile("cp.async.commit_group;" ::: "memory")
#define CP_WAIT(n)  asm volatile("cp.async.wait_group %0;" :: "n"(n) : "memory")

// ---------------- generic utility kernels ----------------
__global__ void zero_f(float* p, int n) {
    int i = blockIdx.x * blockDim.x + threadIdx.x;
    if (i < n) p[i] = 0.f;
}
__global__ void zero_f2(float* p1, float* p2, int n) {
    int i = blockIdx.x * blockDim.x + threadIdx.x;
    if (i < n) { p1[i] = 0.f; p2[i] = 0.f; }
}
__global__ void zero_i(int* p, int n) {
    int i = blockIdx.x * blockDim.x + threadIdx.x;
    if (i < n) p[i] = 0;
}

// transpose W[K,N] -> Wt[N,K] as bf16 hi/lo
__global__ void wsplit(const float* __restrict__ W, __nv_bfloat16* __restrict__ hi,
                       __nv_bfloat16* __restrict__ lo, int K, int N) {
    int i = blockIdx.x * blockDim.x + threadIdx.x;
    if (i >= K * N) return;
    int k = i / N, n = i % N;
    float v = W[i];
    __nv_bfloat16 h = __float2bfloat16(v);
    hi[n * K + k] = h;
    lo[n * K + k] = __float2bfloat16(v - __bfloat162float(h));
}

// ---------------- mma.sync bf16x2-split GEMM: C = A[M,K] @ Wt[N,K]^T ----------------
// CTA tile 256(M)x128(N), K chunk 64, cp.async double-buffered.
// 8 warps = 4(M) x 2(N), warp tile 64x64.
#define ASTR 72   // padded smem row stride (bf16 elems)
#define A_ELEMS (256 * ASTR)
#define B_ELEMS (128 * ASTR)
#define OFF_ALO (A_ELEMS * 2)            // bytes
#define OFF_BHI (2 * A_ELEMS * 2)
#define OFF_BLO (2 * A_ELEMS * 2 + B_ELEMS * 2)
#define BUF_BYTES (2 * (A_ELEMS + B_ELEMS) * 2)   // 110592
#define SMEM_MMA (2 * BUF_BYTES)                  // 221184

template <bool RELU, bool WF32, bool WB16, bool ESED>
__global__ void __launch_bounds__(256, 1) gemm_mma_kernel(
    const __nv_bfloat16* __restrict__ Ahi, const __nv_bfloat16* __restrict__ Alo,
    const __nv_bfloat16* __restrict__ Bhi, const __nv_bfloat16* __restrict__ Blo,
    const float* __restrict__ bias, float* __restrict__ C,
    __nv_bfloat16* __restrict__ Chi, __nv_bfloat16* __restrict__ Clo,
    const float* __restrict__ a_s, const float* __restrict__ a_d,
    float* __restrict__ es, float* __restrict__ ed,
    int M, int K, int N) {
    extern __shared__ __nv_bfloat16 sm[];
    const int tid = threadIdx.x;
    const int wid = tid >> 5, lane = tid & 31;
    const int tile0 = blockIdx.y * 256;   // M offset
    const int col0 = blockIdx.x * 128;    // N offset
    const int mbase = (wid & 3) * 64;     // warp M offset within tile
    const int nbase = (wid >> 2) * 64;    // warp N offset within tile
    const uint32_t base0 = smem_u32(sm);

    float acc[4][8][4];
#pragma unroll
    for (int i = 0; i < 4; i++)
#pragma unroll
        for (int j = 0; j < 8; j++)
#pragma unroll
            for (int r = 0; r < 4; r++) acc[i][j][r] = 0.f;

    const int lrow = (lane & 7) + 8 * ((lane >> 3) & 1);
    const int lcol = 8 * (lane >> 4);
    const int nchunks = K >> 6;

    auto stage = [&](int c, int b) {
        const uint32_t bb = base0 + b * BUF_BYTES;
        const int k0 = c << 6;
#pragma unroll
        for (int it = 0; it < 8; it++) {
            int f = tid + it * 256;
            int r = f >> 3, q = (f & 7) * 8;
            int rg = min(tile0 + r, M - 1);
            uint32_t sw = (uint32_t)(r * ASTR + q) * 2;
            cp16(bb + sw,           Ahi + (size_t)rg * K + k0 + q);
            cp16(bb + OFF_ALO + sw, Alo + (size_t)rg * K + k0 + q);
        }
#pragma unroll
        for (int it = 0; it < 4; it++) {
            int f = tid + it * 256;
            int r = f >> 3, q = (f & 7) * 8;
            int nr = col0 + r;
            uint32_t sw = (uint32_t)(r * ASTR + q) * 2;
            cp16(bb + OFF_BHI + sw, Bhi + (size_t)nr * K + k0 + q);
            cp16(bb + OFF_BLO + sw, Blo + (size_t)nr * K + k0 + q);
        }
    };

    stage(0, 0); CP_COMMIT();

    for (int c = 0; c < nchunks; c++) {
        if (c + 1 < nchunks) {
            stage(c + 1, (c + 1) & 1); CP_COMMIT(); CP_WAIT(1);
        } else {
            CP_WAIT(0);
        }
        __syncthreads();

        const uint32_t bb = base0 + (c & 1) * BUF_BYTES;
        const uint32_t uAh = bb, uAl = bb + OFF_ALO;
        const uint32_t uBh = bb + OFF_BHI, uBl = bb + OFF_BLO;

#pragma unroll
        for (int ks = 0; ks < 4; ks++) {
            const int kk = ks * 16;
            uint32_t ah[4][4], al[4][4], bh[4][4], bl[4][4];
#pragma unroll
            for (int am = 0; am < 4; am++) {
                uint32_t off = (uint32_t)(((mbase + am * 16 + lrow) * ASTR + kk + lcol) * 2);
                ldsm_x4(ah[am], uAh + off);
                ldsm_x4(al[am], uAl + off);
            }
#pragma unroll
            for (int bb2 = 0; bb2 < 4; bb2++) {
                uint32_t off = (uint32_t)(((nbase + bb2 * 16 + lrow) * ASTR + kk + lcol) * 2);
                ldsm_x4(bh[bb2], uBh + off);
                ldsm_x4(bl[bb2], uBl + off);
            }
#pragma unroll
            for (int am = 0; am < 4; am++) {
#pragma unroll
                for (int bb2 = 0; bb2 < 4; bb2++) {
                    mma16816(acc[am][bb2 * 2 + 0], ah[am], bh[bb2][0], bh[bb2][2]);
                    mma16816(acc[am][bb2 * 2 + 1], ah[am], bh[bb2][1], bh[bb2][3]);
                    mma16816(acc[am][bb2 * 2 + 0], ah[am], bl[bb2][0], bl[bb2][2]);
                    mma16816(acc[am][bb2 * 2 + 1], ah[am], bl[bb2][1], bl[bb2][3]);
                    mma16816(acc[am][bb2 * 2 + 0], al[am], bh[bb2][0], bh[bb2][2]);
                    mma16816(acc[am][bb2 * 2 + 1], al[am], bh[bb2][1], bh[bb2][3]);
                }
            }
        }
        __syncthreads();
    }

    // preload attention vector slices (head = blockIdx.x when N == W3)
    float asv[8][2], adv[8][2];
    if (ESED) {
        const int head = blockIdx.x;
#pragma unroll
        for (int an = 0; an < 8; an++) {
            int cl = nbase + an * 8 + (lane & 3) * 2;
#pragma unroll
            for (int j = 0; j < 2; j++) {
                asv[an][j] = a_s[head * HID + cl + j];
                adv[an][j] = a_d[head * HID + cl + j];
            }
        }
    }

#pragma unroll
    for (int am = 0; am < 4; am++) {
#pragma unroll
        for (int h = 0; h < 2; h++) {
            int row = tile0 + mbase + am * 16 + (lane >> 2) + h * 8;
            bool ok = row < M;
            float se_s = 0.f, se_d = 0.f;
#pragma unroll
            for (int an = 0; an < 8; an++) {
                int col = col0 + nbase + an * 8 + (lane & 3) * 2;
                float v0 = acc[am][an][h * 2 + 0] + (bias ? bias[col + 0] : 0.f);
                float v1 = acc[am][an][h * 2 + 1] + (bias ? bias[col + 1] : 0.f);
                if (RELU) { v0 = fmaxf(v0, 0.f); v1 = fmaxf(v1, 0.f); }
                if (ok) {
                    if (WF32) {
                        float2 f2; f2.x = v0; f2.y = v1;
                        *(float2*)(C + (size_t)row * N + col) = f2;
                    }
                    if (WB16) {
                        __nv_bfloat16 h0 = __float2bfloat16(v0);
                        __nv_bfloat16 h1 = __float2bfloat16(v1);
                        __nv_bfloat162 hh; hh.x = h0; hh.y = h1;
                        __nv_bfloat162 ll;
                        ll.x = __float2bfloat16(v0 - __bfloat162float(h0));
                        ll.y = __float2bfloat16(v1 - __bfloat162float(h1));
                        *(__nv_bfloat162*)(Chi + (size_t)row * N + col) = hh;
                        *(__nv_bfloat162*)(Clo + (size_t)row * N + col) = ll;
                    }
                }
                if (ESED) {
                    se_s = fmaf(v0, asv[an][0], fmaf(v1, asv[an][1], se_s));
                    se_d = fmaf(v0, adv[an][0], fmaf(v1, adv[an][1], se_d));
                }
            }
            if (ESED) {
                se_s += __shfl_xor_sync(0xffffffffu, se_s, 1);
                se_s += __shfl_xor_sync(0xffffffffu, se_s, 2);
                se_d += __shfl_xor_sync(0xffffffffu, se_d, 1);
                se_d += __shfl_xor_sync(0xffffffffu, se_d, 2);
                if (ok && (lane & 3) == 0) {
                    atomicAdd(&es[row * 3 + blockIdx.x], se_s);
                    atomicAdd(&ed[row * 3 + blockIdx.x], se_d);
                }
            }
        }
    }
}

// ---------------- fp32 GEMM (lin1 w/ bf16 split out, lin3) ----------------
template <bool RELU, bool WB16>
__global__ void gemm_kernel(const float* __restrict__ A, const float* __restrict__ B,
                            const float* __restrict__ bias, float* __restrict__ C,
                            __nv_bfloat16* __restrict__ Chi, __nv_bfloat16* __restrict__ Clo,
                            int M, int K, int Nc) {
    __shared__ float As[8][128];
    __shared__ float Bs[8][128];
    const int tid = threadIdx.x;
    const int tx = tid & 15, ty = tid >> 4;
    const int row0 = blockIdx.y * 128;
    const int col0 = blockIdx.x * 128;
    float acc[8][8];
#pragma unroll
    for (int i = 0; i < 8; i++)
#pragma unroll
        for (int j = 0; j < 8; j++) acc[i][j] = 0.f;

    for (int k0 = 0; k0 < K; k0 += 8) {
#pragma unroll
        for (int i = 0; i < 4; i++) {
            int flat = tid + i * 256;
            int r = flat >> 3, kk = flat & 7;
            int gr = row0 + r;
            As[kk][r] = (gr < M) ? A[(size_t)gr * K + k0 + kk] : 0.f;
        }
#pragma unroll
        for (int i = 0; i < 4; i++) {
            int flat = tid + i * 256;
            int kk = flat >> 7, cc = flat & 127;
            Bs[kk][cc] = B[(size_t)(k0 + kk) * Nc + col0 + cc];
        }
        __syncthreads();
#pragma unroll
        for (int kk = 0; kk < 8; kk++) {
            float a[8], b[8];
#pragma unroll
            for (int i = 0; i < 8; i++) a[i] = As[kk][ty + 16 * i];
#pragma unroll
            for (int j = 0; j < 8; j++) b[j] = Bs[kk][tx + 16 * j];
#pragma unroll
            for (int i = 0; i < 8; i++)
#pragma unroll
                for (int j = 0; j < 8; j++) acc[i][j] = fmaf(a[i], b[j], acc[i][j]);
        }
        __syncthreads();
    }
#pragma unroll
    for (int i = 0; i < 8; i++) {
        int gr = row0 + ty + 16 * i;
        if (gr >= M) continue;
#pragma unroll
        for (int j = 0; j < 8; j++) {
            int gc = col0 + tx + 16 * j;
            float v = acc[i][j] + (bias ? bias[gc] : 0.f);
            if (RELU) v = fmaxf(v, 0.f);
            if (WB16) {
                __nv_bfloat16 h = __float2bfloat16(v);
                Chi[(size_t)gr * Nc + gc] = h;
                Clo[(size_t)gr * Nc + gc] = __float2bfloat16(v - __bfloat162float(h));
            } else {
                C[(size_t)gr * Nc + gc] = v;
            }
        }
    }
}

// ---------------- CSR build ----------------
__global__ void count_deg(const int* __restrict__ ei, int* __restrict__ deg) {
    int e = blockIdx.x * blockDim.x + threadIdx.x;
    if (e >= ETOT) return;
    int d = (e < EE) ? ei[EE + e] : (e - EE);
    atomicAdd(&deg[d], 1);
}
__global__ void scan_block(const int* __restrict__ deg, int* __restrict__ incl, int* __restrict__ bsum) {
    __shared__ int sh[1024];
    int i = blockIdx.x * 1024 + threadIdx.x;
    sh[threadIdx.x] = (i < NN) ? deg[i] : 0;
    __syncthreads();
#pragma unroll
    for (int o = 1; o < 1024; o <<= 1) {
        int t = (threadIdx.x >= o) ? sh[threadIdx.x - o] : 0;
        __syncthreads();
        sh[threadIdx.x] += t;
        __syncthreads();
    }
    if (i < NN) incl[i] = sh[threadIdx.x];
    if (threadIdx.x == 1023) bsum[blockIdx.x] = sh[1023];
}
__global__ void scan_bsum(int* bsum, int nb) {
    if (blockIdx.x == 0 && threadIdx.x == 0) {
        int run = 0;
        for (int i = 0; i < nb; i++) { int v = bsum[i]; bsum[i] = run; run += v; }
    }
}
__global__ void scan_final(const int* __restrict__ deg, const int* __restrict__ incl,
                           const int* __restrict__ bsum, int* __restrict__ off,
                           int* __restrict__ cur) {
    int i = blockIdx.x * 1024 + threadIdx.x;
    if (i < NN) {
        int o = incl[i] - deg[i] + bsum[blockIdx.x];
        off[i] = o;
        cur[i] = o;
    }
}
__global__ void csr_fill(const int* __restrict__ ei, int* __restrict__ cur, int* __restrict__ csr) {
    int e = blockIdx.x * blockDim.x + threadIdx.x;
    if (e >= ETOT) return;
    int d = (e < EE) ? ei[EE + e] : (e - EE);
    int pos = atomicAdd(&cur[d], 1);
    csr[pos] = e;
}

// ---------------- CSR-ordered attention: per-node softmax, no atomics ----------------
// Pass 1 gathers scattered es[src] once, stashing leaky logits sequentially in alpha;
// passes 2-3 are fully sequential re-reads of alpha.
__global__ void attn_csr(const int* __restrict__ ei, const int* __restrict__ csr,
                         const int* __restrict__ off, const int* __restrict__ deg,
                         const float* __restrict__ es, const float* __restrict__ ed,
                         float* __restrict__ alpha) {
    int n = blockIdx.x * blockDim.x + threadIdx.x;
    if (n >= NN) return;
    int beg = off[n], end = beg + deg[n];
    float d0 = ed[n * 3 + 0], d1 = ed[n * 3 + 1], d2 = ed[n * 3 + 2];
    float m0 = -1e30f, m1 = -1e30f, m2 = -1e30f;
    for (int i = beg; i < end; i++) {
        int e = csr[i];
        int s = (e < EE) ? ei[e] : (e - EE);
        float v0 = es[s * 3 + 0] + d0; v0 = (v0 > 0.f) ? v0 : NEG_SLOPE * v0;
        float v1 = es[s * 3 + 1] + d1; v1 = (v1 > 0.f) ? v1 : NEG_SLOPE * v1;
        float v2 = es[s * 3 + 2] + d2; v2 = (v2 > 0.f) ? v2 : NEG_SLOPE * v2;
        alpha[i * 3 + 0] = v0; alpha[i * 3 + 1] = v1; alpha[i * 3 + 2] = v2;
        m0 = fmaxf(m0, v0); m1 = fmaxf(m1, v1); m2 = fmaxf(m2, v2);
    }
    float s0 = 0.f, s1 = 0.f, s2 = 0.f;
    for (int i = beg; i < end; i++) {
        float p0 = __expf(alpha[i * 3 + 0] - m0);
        float p1 = __expf(alpha[i * 3 + 1] - m1);
        float p2 = __expf(alpha[i * 3 + 2] - m2);
        alpha[i * 3 + 0] = p0; alpha[i * 3 + 1] = p1; alpha[i * 3 + 2] = p2;
        s0 += p0; s1 += p1; s2 += p2;
    }
    float i0 = 1.f / s0, i1 = 1.f / s1, i2 = 1.f / s2;
    for (int i = beg; i < end; i++) {
        alpha[i * 3 + 0] *= i0;
        alpha[i * 3 + 1] *= i1;
        alpha[i * 3 + 2] *= i2;
    }
}

// ---------------- aggregation with fused BN stats ----------------
#define NPB 8
__global__ void __launch_bounds__(W3) aggregate(
    const float* __restrict__ Hf, const int* __restrict__ ei,
    const int* __restrict__ csr, const int* __restrict__ off,
    const int* __restrict__ deg, const float* __restrict__ alpha,
    const float* __restrict__ bias,
    float* __restrict__ out, float* __restrict__ bnsum, float* __restrict__ bnsq) {
    const int c = threadIdx.x;            // 0..383
    const int h = c >> 7;                 // head
    const int n0 = blockIdx.x * NPB;
    const float bcol = bias[c];
    float s = 0.f, q = 0.f;
#pragma unroll 1
    for (int k = 0; k < NPB; k++) {
        int n = n0 + k;
        float a = 0.f;
        int beg = off[n], end = beg + deg[n];
        for (int i = beg; i < end; i++) {
            int e = csr[i];
            int sidx = (e < EE) ? ei[e] : (e - EE);
            a = fmaf(alpha[i * 3 + h], Hf[(size_t)sidx * W3 + c], a);
        }
        float v = a + bcol;
        out[(size_t)n * W3 + c] = v;
        s += v;
        q = fmaf(v, v, q);
    }
    atomicAdd(&bnsum[c], s);
    atomicAdd(&bnsq[c], q);
}

// ---------------- batch norm ----------------
__global__ void bn_coef(const float* __restrict__ sum, const float* __restrict__ sq,
                        const float* __restrict__ gamma, const float* __restrict__ beta,
                        float* __restrict__ scale, float* __restrict__ shift) {
    int c = threadIdx.x;
    float mu = sum[c] * (1.f / NN);
    float var = sq[c] * (1.f / NN) - mu * mu;
    float sc = rsqrtf(var + 1e-5f) * gamma[c];
    scale[c] = sc;
    shift[c] = beta[c] - mu * sc;
}
__global__ void bn_apply_b16(const float* __restrict__ x, const float* __restrict__ scale,
                             const float* __restrict__ shift,
                             __nv_bfloat16* __restrict__ hi, __nv_bfloat16* __restrict__ lo) {
    int c = threadIdx.x;
    int n = blockIdx.x;
    size_t i = (size_t)n * W3 + c;
    float v = fmaf(x[i], scale[c], shift[c]);
    __nv_bfloat16 h = __float2bfloat16(v);
    hi[i] = h;
    lo[i] = __float2bfloat16(v - __bfloat162float(h));
}

// ---------------- pooling + head ----------------
__global__ void pool_add(const float* __restrict__ x, const int* __restrict__ batch,
                         float* __restrict__ pool) {
    int n = blockIdx.x;
    int c = threadIdx.x;
    atomicAdd(&pool[(size_t)batch[n] * W3 + c], x[(size_t)n * W3 + c]);
}
__global__ void cnt_add(const int* __restrict__ batch, float* __restrict__ cnt) {
    int n = blockIdx.x * blockDim.x + threadIdx.x;
    if (n < NN) atomicAdd(&cnt[batch[n]], 1.f);
}
// mean + layer-3 BN affine folded in (mean(BN(x)) == BN(mean(x)))
__global__ void pool_div_bn(float* __restrict__ pool, const float* __restrict__ cnt,
                            const float* __restrict__ scale, const float* __restrict__ shift) {
    int g = blockIdx.x;
    int c = threadIdx.x;
    float m = pool[(size_t)g * W3 + c] / fmaxf(cnt[g], 1.f);
    pool[(size_t)g * W3 + c] = fmaf(m, scale[c], shift[c]);
}
__global__ void head_kernel(const float* __restrict__ g2, const float* __restrict__ w4,
                            const float* __restrict__ b4, float* __restrict__ out) {
    int g = blockIdx.x * blockDim.x + threadIdx.x;
    if (g >= GG) return;
    float acc[NC];
#pragma unroll
    for (int j = 0; j < NC; j++) acc[j] = b4[j];
    for (int c = 0; c < HID; c++) {
        float v = g2[(size_t)g * HID + c];
#pragma unroll
        for (int j = 0; j < NC; j++) acc[j] = fmaf(v, w4[c * NC + j], acc[j]);
    }
    float mx = acc[0];
#pragma unroll
    for (int j = 1; j < NC; j++) mx = fmaxf(mx, acc[j]);
    float se = 0.f;
#pragma unroll
    for (int j = 0; j < NC; j++) se += expf(acc[j] - mx);
    float l = logf(se) + mx;
#pragma unroll
    for (int j = 0; j < NC; j++) out[(size_t)g * NC + j] = acc[j] - l;
}

extern "C" void kernel_launch(void* const* d_in, const int* in_sizes, int n_in,
                              void* d_out, int out_size) {
    const float* x      = (const float*)d_in[0];
    const int*   ei     = (const int*)d_in[1];
    const int*   batch  = (const int*)d_in[2];
    const float* lin1_w = (const float*)d_in[3];
    const float* lin1_b = (const float*)d_in[4];
    const float* lin2_w = (const float*)d_in[5];
    const float* lin2_b = (const float*)d_in[6];
    const float* w0     = (const float*)d_in[7];
    const float* as0    = (const float*)d_in[8];
    const float* ad0    = (const float*)d_in[9];
    const float* b0     = (const float*)d_in[10];
    const float* wl     = (const float*)d_in[11];
    const float* asl    = (const float*)d_in[12];
    const float* adl    = (const float*)d_in[13];
    const float* bl     = (const float*)d_in[14];
    const float* gamma  = (const float*)d_in[15];
    const float* beta   = (const float*)d_in[16];
    const float* lin3_w = (const float*)d_in[17];
    const float* lin3_b = (const float*)d_in[18];
    const float* lin4_w = (const float*)d_in[19];
    const float* lin4_b = (const float*)d_in[20];
    float* out = (float*)d_out;

    float *pA, *pB, *pH, *pes, *ped, *palpha, *ppool, *pcnt, *pg2;
    float *pbnsum, *pbnsq, *pscale, *pshift;
    int *pdeg, *poff, *pcur, *pincl, *pbs, *pcsr;
    __nv_bfloat16 *pXhi, *pXlo, *pYhi, *pYlo, *pWhi, *pWlo;
    cudaGetSymbolAddress((void**)&pA, g_bufA);
    cudaGetSymbolAddress((void**)&pB, g_bufB);
    cudaGetSymbolAddress((void**)&pH, g_Hf);
    cudaGetSymbolAddress((void**)&pXhi, g_Xhi);
    cudaGetSymbolAddress((void**)&pXlo, g_Xlo);
    cudaGetSymbolAddress((void**)&pYhi, g_Yhi);
    cudaGetSymbolAddress((void**)&pYlo, g_Ylo);
    cudaGetSymbolAddress((void**)&pWhi, g_Whi);
    cudaGetSymbolAddress((void**)&pWlo, g_Wlo);
    cudaGetSymbolAddress((void**)&pes, g_es);
    cudaGetSymbolAddress((void**)&ped, g_ed);
    cudaGetSymbolAddress((void**)&palpha, g_p);
    cudaGetSymbolAddress((void**)&pdeg, g_deg);
    cudaGetSymbolAddress((void**)&poff, g_off);
    cudaGetSymbolAddress((void**)&pcur, g_cur);
    cudaGetSymbolAddress((void**)&pincl, g_incl);
    cudaGetSymbolAddress((void**)&pbs, g_bsum);
    cudaGetSymbolAddress((void**)&pcsr, g_csr);
    cudaGetSymbolAddress((void**)&ppool, g_pool);
    cudaGetSymbolAddress((void**)&pcnt, g_cnt);
    cudaGetSymbolAddress((void**)&pg2, g_g2);
    cudaGetSymbolAddress((void**)&pbnsum, g_bnsum);
    cudaGetSymbolAddress((void**)&pbnsq, g_bnsq);
    cudaGetSymbolAddress((void**)&pscale, g_scale);
    cudaGetSymbolAddress((void**)&pshift, g_shift);

    cudaFuncSetAttribute(gemm_mma_kernel<true, false, true, false>,
                         cudaFuncAttributeMaxDynamicSharedMemorySize, SMEM_MMA);
    cudaFuncSetAttribute(gemm_mma_kernel<false, true, false, true>,
                         cudaFuncAttributeMaxDynamicSharedMemorySize, SMEM_MMA);

    const int MB128 = (NN + 127) / 128;   // 782
    const int MB256 = (NN + 255) / 256;   // 391

    // ---- MLP stem ----
    {   // lin1: fp32 gemm, emit bf16 hi/lo directly (relu applied)
        dim3 grid(2, MB128);
        gemm_kernel<true, true><<<grid, 256>>>(x, lin1_w, lin1_b, nullptr,
                                               pXhi, pXlo, NN, F_IN, 2 * HID);
    }
    wsplit<<<(256 * 128 + 255) / 256, 256>>>(lin2_w, pWhi, pWlo, 256, 128);
    {   // lin2: tensor gemm, relu, emit bf16 hi/lo into Y
        dim3 grid(1, MB256);
        gemm_mma_kernel<true, false, true, false><<<grid, 256, SMEM_MMA>>>(
            pXhi, pXlo, pWhi, pWlo, lin2_b, nullptr, pYhi, pYlo,
            nullptr, nullptr, nullptr, nullptr, NN, 256, 128);
    }

    // ---- CSR build (by dst) ----
    zero_i<<<(NN + 255) / 256, 256>>>(pdeg, NN);
    count_deg<<<(ETOT + 255) / 256, 256>>>(ei, pdeg);
    const int NB = (NN + 1023) / 1024;
    scan_block<<<NB, 1024>>>(pdeg, pincl, pbs);
    scan_bsum<<<1, 32>>>(pbs, NB);
    scan_final<<<NB, 1024>>>(pdeg, pincl, pbs, poff, pcur);
    csr_fill<<<(ETOT + 255) / 256, 256>>>(ei, pcur, pcsr);

    // ---- GAT layers ----
    float* Xin = pA;
    float* Xout = pB;
    for (int l = 0; l < 4; l++) {
        const float* W    = (l == 0) ? w0  : wl  + (size_t)(l - 1) * W3 * W3;
        const float* a_s  = (l == 0) ? as0 : asl + (l - 1) * 3 * HID;
        const float* a_d  = (l == 0) ? ad0 : adl + (l - 1) * 3 * HID;
        const float* bias = (l == 0) ? b0  : bl  + (l - 1) * W3;
        const int K       = (l == 0) ? HID : W3;
        const __nv_bfloat16* Ah = (l == 0) ? pYhi : pXhi;
        const __nv_bfloat16* Al = (l == 0) ? pYlo : pXlo;

        wsplit<<<(K * W3 + 255) / 256, 256>>>(W, pWhi, pWlo, K, W3);
        zero_f2<<<(NN * 3 + 255) / 256, 256>>>(pes, ped, NN * 3);
        {
            dim3 grid(3, MB256);
            gemm_mma_kernel<false, true, false, true><<<grid, 256, SMEM_MMA>>>(
                Ah, Al, pWhi, pWlo, nullptr, pH, nullptr, nullptr,
                a_s, a_d, pes, ped, NN, K, W3);
        }

        attn_csr<<<(NN + 255) / 256, 256>>>(ei, pcsr, poff, pdeg, pes, ped, palpha);

        zero_f2<<<3, 256>>>(pbnsum, pbnsq, W3);
        aggregate<<<NN / NPB, W3>>>(pH, ei, pcsr, poff, pdeg, palpha, bias,
                                    Xout, pbnsum, pbnsq);
        bn_coef<<<1, W3>>>(pbnsum, pbnsq, gamma + l * W3, beta + l * W3, pscale, pshift);
        if (l < 3)
            bn_apply_b16<<<NN, W3>>>(Xout, pscale, pshift, pXhi, pXlo);
        // layer 3: BN affine folded into pool_div_bn

        float* t = Xin; Xin = Xout; Xout = t;
    }

    // ---- global mean pool (+ layer-3 BN affine) ----
    zero_f<<<(GG * W3 + 255) / 256, 256>>>(ppool, GG * W3);
    zero_f<<<(GG + 255) / 256, 256>>>(pcnt, GG);
    pool_add<<<NN, W3>>>(Xin, batch, ppool);
    cnt_add<<<(NN + 255) / 256, 256>>>(batch, pcnt);
    pool_div_bn<<<GG, W3>>>(ppool, pcnt, pscale, pshift);

    // ---- head ----
    {
        dim3 grid(1, (GG + 127) / 128);
        gemm_kernel<true, false><<<grid, 256>>>(ppool, lin3_w, lin3_b, pg2,
                                                nullptr, nullptr, GG, W3, HID);
    }
    head_kernel<<<(GG + 127) / 128, 128>>>(pg2, lin4_w, lin4_b, out);
}

// round 12
// speedup vs baseline: 1.5391x; 1.1553x over previous
#include <cuda_runtime.h>
#include <cuda_bf16.h>
#include <cstdint>
#include <math.h>

// ---------------- problem constants ----------------
#define NN    100000
#define EE    400000
#define ETOT  500000   // EE + NN self loops
#define GG    4000
#define F_IN  32
#define HID   128
#define W3    384
#define NC    10
#define NEG_SLOPE 0.2f

// ---------------- scratch (device globals; no allocations allowed) ----------------
__device__ float          g_bufA[NN * W3];
__device__ float          g_Hf  [NN * W3];
__device__ __nv_bfloat16  g_Xhi [NN * W3];
__device__ __nv_bfloat16  g_Xlo [NN * W3];
__device__ __nv_bfloat16  g_Yhi [NN * HID];
__device__ __nv_bfloat16  g_Ylo [NN * HID];
__device__ __nv_bfloat16  g_Whi [W3 * W3];
__device__ __nv_bfloat16  g_Wlo [W3 * W3];
__device__ float          g_es  [NN * 3];
__device__ float          g_ed  [NN * 3];
__device__ float          g_p   [ETOT * 3];   // logits -> exp -> normalized alpha (CSR order)
__device__ int            g_deg [NN];
__device__ int            g_off [NN];
__device__ int            g_cur [NN];
__device__ int            g_incl[NN];
__device__ int            g_bsum[128];
__device__ int            g_csr [ETOT];
__device__ float          g_pool[GG * W3];
__device__ float          g_cnt [GG];
__device__ float          g_g2  [GG * HID];
__device__ float          g_bnsum[W3];
__device__ float          g_bnsq [W3];
__device__ float          g_scale[W3];
__device__ float          g_shift[W3];
__device__ float          g_gbias[W3];

// ---------------- helpers ----------------
__device__ __forceinline__ uint32_t smem_u32(const void* p) {
    uint32_t a;
    asm("{ .reg .u64 t; cvta.to.shared.u64 t, %1; cvt.u32.u64 %0, t; }" : "=r"(a) : "l"(p));
    return a;
}
__device__ __forceinline__ void ldsm_x4(uint32_t* r, uint32_t addr) {
    asm volatile("ldmatrix.sync.aligned.m8n8.x4.shared.b16 {%0,%1,%2,%3}, [%4];"
                 : "=r"(r[0]), "=r"(r[1]), "=r"(r[2]), "=r"(r[3]) : "r"(addr));
}
__device__ __forceinline__ void mma16816(float* c, const uint32_t* a, uint32_t b0, uint32_t b1) {
    asm volatile(
        "mma.sync.aligned.m16n8k16.row.col.f32.bf16.bf16.f32 "
        "{%0,%1,%2,%3}, {%4,%5,%6,%7}, {%8,%9}, {%0,%1,%2,%3};"
        : "+f"(c[0]), "+f"(c[1]), "+f"(c[2]), "+f"(c[3])
        : "r"(a[0]), "r"(a[1]), "r"(a[2]), "r"(a[3]), "r"(b0), "r"(b1));
}
__device__ __forceinline__ void cp16(uint32_t smem, const void* g) {
    asm volatile("cp.async.cg.shared.global [%0], [%1], 16;" :: "r"(smem), "l"(g));
}
#define CP_COMMIT() asm volatile("cp.async.commit_group;" ::: "memory")
#define CP_WAIT(n)  asm volatile("cp.async.wait_group %0;" :: "n"(n) : "memory")

// ---------------- generic utility kernels ----------------
__global__ void zero_f(float* p, int n) {
    int i = blockIdx.x * blockDim.x + threadIdx.x;
    if (i < n) p[i] = 0.f;
}
__global__ void zero_f2(float* p1, float* p2, int n) {
    int i = blockIdx.x * blockDim.x + threadIdx.x;
    if (i < n) { p1[i] = 0.f; p2[i] = 0.f; }
}
__global__ void zero_i(int* p, int n) {
    int i = blockIdx.x * blockDim.x + threadIdx.x;
    if (i < n) p[i] = 0;
}

// transpose W[K,N] -> Wt[N,K] as bf16 hi/lo
__global__ void wsplit(const float* __restrict__ W, __nv_bfloat16* __restrict__ hi,
                       __nv_bfloat16* __restrict__ lo, int K, int N) {
    int i = blockIdx.x * blockDim.x + threadIdx.x;
    if (i >= K * N) return;
    int k = i / N, n = i % N;
    float v = W[i];
    __nv_bfloat16 h = __float2bfloat16(v);
    hi[n * K + k] = h;
    lo[n * K + k] = __float2bfloat16(v - __bfloat162float(h));
}
// same, with per-K BN scale folded in (W' = diag(scale) @ W)
__global__ void wsplit_bn(const float* __restrict__ W, const float* __restrict__ scale,
                          __nv_bfloat16* __restrict__ hi, __nv_bfloat16* __restrict__ lo) {
    int i = blockIdx.x * blockDim.x + threadIdx.x;
    if (i >= W3 * W3) return;
    int k = i / W3, n = i % W3;
    float v = W[i] * scale[k];
    __nv_bfloat16 h = __float2bfloat16(v);
    hi[n * W3 + k] = h;
    lo[n * W3 + k] = __float2bfloat16(v - __bfloat162float(h));
}
// rank-1 bias from BN shift: gb[n] = sum_k shift[k] * W[k, n]
__global__ void gbias_kernel(const float* __restrict__ W, const float* __restrict__ shift,
                             float* __restrict__ gb) {
    int n = blockIdx.x * blockDim.x + threadIdx.x;
    if (n >= W3) return;
    float s = 0.f;
    for (int k = 0; k < W3; k++) s = fmaf(shift[k], W[(size_t)k * W3 + n], s);
    gb[n] = s;
}

// ---------------- mma.sync bf16x2-split GEMM: C = A[M,K] @ Wt[N,K]^T ----------------
// CTA tile 256(M)x128(N), K chunk 64, cp.async double-buffered.
// 8 warps = 4(M) x 2(N), warp tile 64x64.
#define ASTR 72   // padded smem row stride (bf16 elems)
#define A_ELEMS (256 * ASTR)
#define B_ELEMS (128 * ASTR)
#define OFF_ALO (A_ELEMS * 2)            // bytes
#define OFF_BHI (2 * A_ELEMS * 2)
#define OFF_BLO (2 * A_ELEMS * 2 + B_ELEMS * 2)
#define BUF_BYTES (2 * (A_ELEMS + B_ELEMS) * 2)   // 110592
#define SMEM_MMA (2 * BUF_BYTES)                  // 221184

template <bool RELU, bool WF32, bool WB16, bool ESED>
__global__ void __launch_bounds__(256, 1) gemm_mma_kernel(
    const __nv_bfloat16* __restrict__ Ahi, const __nv_bfloat16* __restrict__ Alo,
    const __nv_bfloat16* __restrict__ Bhi, const __nv_bfloat16* __restrict__ Blo,
    const float* __restrict__ bias, float* __restrict__ C,
    __nv_bfloat16* __restrict__ Chi, __nv_bfloat16* __restrict__ Clo,
    const float* __restrict__ a_s, const float* __restrict__ a_d,
    float* __restrict__ es, float* __restrict__ ed,
    int M, int K, int N) {
    extern __shared__ __nv_bfloat16 sm[];
    const int tid = threadIdx.x;
    const int wid = tid >> 5, lane = tid & 31;
    const int tile0 = blockIdx.y * 256;   // M offset
    const int col0 = blockIdx.x * 128;    // N offset
    const int mbase = (wid & 3) * 64;     // warp M offset within tile
    const int nbase = (wid >> 2) * 64;    // warp N offset within tile
    const uint32_t base0 = smem_u32(sm);

    float acc[4][8][4];
#pragma unroll
    for (int i = 0; i < 4; i++)
#pragma unroll
        for (int j = 0; j < 8; j++)
#pragma unroll
            for (int r = 0; r < 4; r++) acc[i][j][r] = 0.f;

    const int lrow = (lane & 7) + 8 * ((lane >> 3) & 1);
    const int lcol = 8 * (lane >> 4);
    const int nchunks = K >> 6;

    auto stage = [&](int c, int b) {
        const uint32_t bb = base0 + b * BUF_BYTES;
        const int k0 = c << 6;
#pragma unroll
        for (int it = 0; it < 8; it++) {
            int f = tid + it * 256;
            int r = f >> 3, q = (f & 7) * 8;
            int rg = min(tile0 + r, M - 1);
            uint32_t sw = (uint32_t)(r * ASTR + q) * 2;
            cp16(bb + sw,           Ahi + (size_t)rg * K + k0 + q);
            cp16(bb + OFF_ALO + sw, Alo + (size_t)rg * K + k0 + q);
        }
#pragma unroll
        for (int it = 0; it < 4; it++) {
            int f = tid + it * 256;
            int r = f >> 3, q = (f & 7) * 8;
            int nr = col0 + r;
            uint32_t sw = (uint32_t)(r * ASTR + q) * 2;
            cp16(bb + OFF_BHI + sw, Bhi + (size_t)nr * K + k0 + q);
            cp16(bb + OFF_BLO + sw, Blo + (size_t)nr * K + k0 + q);
        }
    };

    stage(0, 0); CP_COMMIT();

    for (int c = 0; c < nchunks; c++) {
        if (c + 1 < nchunks) {
            stage(c + 1, (c + 1) & 1); CP_COMMIT(); CP_WAIT(1);
        } else {
            CP_WAIT(0);
        }
        __syncthreads();

        const uint32_t bb = base0 + (c & 1) * BUF_BYTES;
        const uint32_t uAh = bb, uAl = bb + OFF_ALO;
        const uint32_t uBh = bb + OFF_BHI, uBl = bb + OFF_BLO;

#pragma unroll
        for (int ks = 0; ks < 4; ks++) {
            const int kk = ks * 16;
            uint32_t ah[4][4], al[4][4], bh[4][4], bl[4][4];
#pragma unroll
            for (int am = 0; am < 4; am++) {
                uint32_t off = (uint32_t)(((mbase + am * 16 + lrow) * ASTR + kk + lcol) * 2);
                ldsm_x4(ah[am], uAh + off);
                ldsm_x4(al[am], uAl + off);
            }
#pragma unroll
            for (int bb2 = 0; bb2 < 4; bb2++) {
                uint32_t off = (uint32_t)(((nbase + bb2 * 16 + lrow) * ASTR + kk + lcol) * 2);
                ldsm_x4(bh[bb2], uBh + off);
                ldsm_x4(bl[bb2], uBl + off);
            }
#pragma unroll
            for (int am = 0; am < 4; am++) {
#pragma unroll
                for (int bb2 = 0; bb2 < 4; bb2++) {
                    mma16816(acc[am][bb2 * 2 + 0], ah[am], bh[bb2][0], bh[bb2][2]);
                    mma16816(acc[am][bb2 * 2 + 1], ah[am], bh[bb2][1], bh[bb2][3]);
                    mma16816(acc[am][bb2 * 2 + 0], ah[am], bl[bb2][0], bl[bb2][2]);
                    mma16816(acc[am][bb2 * 2 + 1], ah[am], bl[bb2][1], bl[bb2][3]);
                    mma16816(acc[am][bb2 * 2 + 0], al[am], bh[bb2][0], bh[bb2][2]);
                    mma16816(acc[am][bb2 * 2 + 1], al[am], bh[bb2][1], bh[bb2][3]);
                }
            }
        }
        __syncthreads();
    }

    // preload attention vector slices (head = blockIdx.x when N == W3)
    float asv[8][2], adv[8][2];
    if (ESED) {
        const int head = blockIdx.x;
#pragma unroll
        for (int an = 0; an < 8; an++) {
            int cl = nbase + an * 8 + (lane & 3) * 2;
#pragma unroll
            for (int j = 0; j < 2; j++) {
                asv[an][j] = a_s[head * HID + cl + j];
                adv[an][j] = a_d[head * HID + cl + j];
            }
        }
    }

#pragma unroll
    for (int am = 0; am < 4; am++) {
#pragma unroll
        for (int h = 0; h < 2; h++) {
            int row = tile0 + mbase + am * 16 + (lane >> 2) + h * 8;
            bool ok = row < M;
            float se_s = 0.f, se_d = 0.f;
#pragma unroll
            for (int an = 0; an < 8; an++) {
                int col = col0 + nbase + an * 8 + (lane & 3) * 2;
                float v0 = acc[am][an][h * 2 + 0] + (bias ? bias[col + 0] : 0.f);
                float v1 = acc[am][an][h * 2 + 1] + (bias ? bias[col + 1] : 0.f);
                if (RELU) { v0 = fmaxf(v0, 0.f); v1 = fmaxf(v1, 0.f); }
                if (ok) {
                    if (WF32) {
                        float2 f2; f2.x = v0; f2.y = v1;
                        *(float2*)(C + (size_t)row * N + col) = f2;
                    }
                    if (WB16) {
                        __nv_bfloat16 h0 = __float2bfloat16(v0);
                        __nv_bfloat16 h1 = __float2bfloat16(v1);
                        __nv_bfloat162 hh; hh.x = h0; hh.y = h1;
                        __nv_bfloat162 ll;
                        ll.x = __float2bfloat16(v0 - __bfloat162float(h0));
                        ll.y = __float2bfloat16(v1 - __bfloat162float(h1));
                        *(__nv_bfloat162*)(Chi + (size_t)row * N + col) = hh;
                        *(__nv_bfloat162*)(Clo + (size_t)row * N + col) = ll;
                    }
                }
                if (ESED) {
                    se_s = fmaf(v0, asv[an][0], fmaf(v1, asv[an][1], se_s));
                    se_d = fmaf(v0, adv[an][0], fmaf(v1, adv[an][1], se_d));
                }
            }
            if (ESED) {
                se_s += __shfl_xor_sync(0xffffffffu, se_s, 1);
                se_s += __shfl_xor_sync(0xffffffffu, se_s, 2);
                se_d += __shfl_xor_sync(0xffffffffu, se_d, 1);
                se_d += __shfl_xor_sync(0xffffffffu, se_d, 2);
                if (ok && (lane & 3) == 0) {
                    atomicAdd(&es[row * 3 + blockIdx.x], se_s);
                    atomicAdd(&ed[row * 3 + blockIdx.x], se_d);
                }
            }
        }
    }
}

// ---------------- fp32 GEMM (lin1 w/ bf16 split out, lin3) ----------------
template <bool RELU, bool WB16>
__global__ void gemm_kernel(const float* __restrict__ A, const float* __restrict__ B,
                            const float* __restrict__ bias, float* __restrict__ C,
                            __nv_bfloat16* __restrict__ Chi, __nv_bfloat16* __restrict__ Clo,
                            int M, int K, int Nc) {
    __shared__ float As[8][128];
    __shared__ float Bs[8][128];
    const int tid = threadIdx.x;
    const int tx = tid & 15, ty = tid >> 4;
    const int row0 = blockIdx.y * 128;
    const int col0 = blockIdx.x * 128;
    float acc[8][8];
#pragma unroll
    for (int i = 0; i < 8; i++)
#pragma unroll
        for (int j = 0; j < 8; j++) acc[i][j] = 0.f;

    for (int k0 = 0; k0 < K; k0 += 8) {
#pragma unroll
        for (int i = 0; i < 4; i++) {
            int flat = tid + i * 256;
            int r = flat >> 3, kk = flat & 7;
            int gr = row0 + r;
            As[kk][r] = (gr < M) ? A[(size_t)gr * K + k0 + kk] : 0.f;
        }
#pragma unroll
        for (int i = 0; i < 4; i++) {
            int flat = tid + i * 256;
            int kk = flat >> 7, cc = flat & 127;
            Bs[kk][cc] = B[(size_t)(k0 + kk) * Nc + col0 + cc];
        }
        __syncthreads();
#pragma unroll
        for (int kk = 0; kk < 8; kk++) {
            float a[8], b[8];
#pragma unroll
            for (int i = 0; i < 8; i++) a[i] = As[kk][ty + 16 * i];
#pragma unroll
            for (int j = 0; j < 8; j++) b[j] = Bs[kk][tx + 16 * j];
#pragma unroll
            for (int i = 0; i < 8; i++)
#pragma unroll
                for (int j = 0; j < 8; j++) acc[i][j] = fmaf(a[i], b[j], acc[i][j]);
        }
        __syncthreads();
    }
#pragma unroll
    for (int i = 0; i < 8; i++) {
        int gr = row0 + ty + 16 * i;
        if (gr >= M) continue;
#pragma unroll
        for (int j = 0; j < 8; j++) {
            int gc = col0 + tx + 16 * j;
            float v = acc[i][j] + (bias ? bias[gc] : 0.f);
            if (RELU) v = fmaxf(v, 0.f);
            if (WB16) {
                __nv_bfloat16 h = __float2bfloat16(v);
                Chi[(size_t)gr * Nc + gc] = h;
                Clo[(size_t)gr * Nc + gc] = __float2bfloat16(v - __bfloat162float(h));
            } else {
                C[(size_t)gr * Nc + gc] = v;
            }
        }
    }
}

// ---------------- CSR build ----------------
__global__ void count_deg(const int* __restrict__ ei, int* __restrict__ deg) {
    int e = blockIdx.x * blockDim.x + threadIdx.x;
    if (e >= ETOT) return;
    int d = (e < EE) ? ei[EE + e] : (e - EE);
    atomicAdd(&deg[d], 1);
}
__global__ void scan_block(const int* __restrict__ deg, int* __restrict__ incl, int* __restrict__ bsum) {
    __shared__ int sh[1024];
    int i = blockIdx.x * 1024 + threadIdx.x;
    sh[threadIdx.x] = (i < NN) ? deg[i] : 0;
    __syncthreads();
#pragma unroll
    for (int o = 1; o < 1024; o <<= 1) {
        int t = (threadIdx.x >= o) ? sh[threadIdx.x - o] : 0;
        __syncthreads();
        sh[threadIdx.x] += t;
        __syncthreads();
    }
    if (i < NN) incl[i] = sh[threadIdx.x];
    if (threadIdx.x == 1023) bsum[blockIdx.x] = sh[1023];
}
__global__ void scan_bsum(int* bsum, int nb) {
    if (blockIdx.x == 0 && threadIdx.x == 0) {
        int run = 0;
        for (int i = 0; i < nb; i++) { int v = bsum[i]; bsum[i] = run; run += v; }
    }
}
__global__ void scan_final(const int* __restrict__ deg, const int* __restrict__ incl,
                           const int* __restrict__ bsum, int* __restrict__ off,
                           int* __restrict__ cur) {
    int i = blockIdx.x * 1024 + threadIdx.x;
    if (i < NN) {
        int o = incl[i] - deg[i] + bsum[blockIdx.x];
        off[i] = o;
        cur[i] = o;
    }
}
__global__ void csr_fill(const int* __restrict__ ei, int* __restrict__ cur, int* __restrict__ csr) {
    int e = blockIdx.x * blockDim.x + threadIdx.x;
    if (e >= ETOT) return;
    int d = (e < EE) ? ei[EE + e] : (e - EE);
    int pos = atomicAdd(&cur[d], 1);
    csr[pos] = e;
}

// ---------------- CSR-ordered attention: per-node softmax, no atomics ----------------
__global__ void attn_csr(const int* __restrict__ ei, const int* __restrict__ csr,
                         const int* __restrict__ off, const int* __restrict__ deg,
                         const float* __restrict__ es, const float* __restrict__ ed,
                         float* __restrict__ alpha) {
    int n = blockIdx.x * blockDim.x + threadIdx.x;
    if (n >= NN) return;
    int beg = off[n], end = beg + deg[n];
    float d0 = ed[n * 3 + 0], d1 = ed[n * 3 + 1], d2 = ed[n * 3 + 2];
    float m0 = -1e30f, m1 = -1e30f, m2 = -1e30f;
    for (int i = beg; i < end; i++) {
        int e = csr[i];
        int s = (e < EE) ? ei[e] : (e - EE);
        float v0 = es[s * 3 + 0] + d0; v0 = (v0 > 0.f) ? v0 : NEG_SLOPE * v0;
        float v1 = es[s * 3 + 1] + d1; v1 = (v1 > 0.f) ? v1 : NEG_SLOPE * v1;
        float v2 = es[s * 3 + 2] + d2; v2 = (v2 > 0.f) ? v2 : NEG_SLOPE * v2;
        alpha[i * 3 + 0] = v0; alpha[i * 3 + 1] = v1; alpha[i * 3 + 2] = v2;
        m0 = fmaxf(m0, v0); m1 = fmaxf(m1, v1); m2 = fmaxf(m2, v2);
    }
    float s0 = 0.f, s1 = 0.f, s2 = 0.f;
    for (int i = beg; i < end; i++) {
        float p0 = __expf(alpha[i * 3 + 0] - m0);
        float p1 = __expf(alpha[i * 3 + 1] - m1);
        float p2 = __expf(alpha[i * 3 + 2] - m2);
        alpha[i * 3 + 0] = p0; alpha[i * 3 + 1] = p1; alpha[i * 3 + 2] = p2;
        s0 += p0; s1 += p1; s2 += p2;
    }
    float i0 = 1.f / s0, i1 = 1.f / s1, i2 = 1.f / s2;
    for (int i = beg; i < end; i++) {
        alpha[i * 3 + 0] *= i0;
        alpha[i * 3 + 1] *= i1;
        alpha[i * 3 + 2] *= i2;
    }
}

// ---------------- aggregation with fused BN stats + staged edge indices ----------------
// Writes pre-BN aggregate as bf16 hi/lo (layers 0-2, BN folded into next W) or fp32 (layer 3).
#define NPB 8
#define ECAP 512
template <bool WF32, bool WB16>
__global__ void __launch_bounds__(W3) aggregate(
    const float* __restrict__ Hf, const int* __restrict__ ei,
    const int* __restrict__ csr, const int* __restrict__ off,
    const int* __restrict__ deg, const float* __restrict__ alpha,
    const float* __restrict__ bias,
    float* __restrict__ out, __nv_bfloat16* __restrict__ hi, __nv_bfloat16* __restrict__ lo,
    float* __restrict__ bnsum, float* __restrict__ bnsq) {
    __shared__ int   s_idx[ECAP];
    __shared__ float s_a[3][ECAP];
    const int c = threadIdx.x;            // 0..383
    const int h = c >> 7;                 // head
    const int n0 = blockIdx.x * NPB;
    const int beg0 = off[n0];
    const int end0 = (n0 + NPB < NN) ? off[n0 + NPB] : ETOT;
    const int total = end0 - beg0;
    const bool fast = (total <= ECAP);
    if (fast) {
        for (int j = c; j < total; j += W3) {
            int e = csr[beg0 + j];
            s_idx[j] = (e < EE) ? ei[e] : (e - EE);
            s_a[0][j] = alpha[(size_t)(beg0 + j) * 3 + 0];
            s_a[1][j] = alpha[(size_t)(beg0 + j) * 3 + 1];
            s_a[2][j] = alpha[(size_t)(beg0 + j) * 3 + 2];
        }
    }
    __syncthreads();
    const float bcol = bias[c];
    float s = 0.f, q = 0.f;
    int jb = 0;
#pragma unroll 1
    for (int k = 0; k < NPB; k++) {
        int n = n0 + k;
        int d = deg[n];
        float a = 0.f;
        if (fast) {
            for (int j = jb; j < jb + d; j++)
                a = fmaf(s_a[h][j], Hf[(size_t)s_idx[j] * W3 + c], a);
            jb += d;
        } else {
            int beg = off[n];
            for (int i = beg; i < beg + d; i++) {
                int e = csr[i];
                int sidx = (e < EE) ? ei[e] : (e - EE);
                a = fmaf(alpha[(size_t)i * 3 + h], Hf[(size_t)sidx * W3 + c], a);
            }
        }
        float v = a + bcol;
        if (WF32) out[(size_t)n * W3 + c] = v;
        if (WB16) {
            __nv_bfloat16 hh = __float2bfloat16(v);
            hi[(size_t)n * W3 + c] = hh;
            lo[(size_t)n * W3 + c] = __float2bfloat16(v - __bfloat162float(hh));
        }
        s += v;
        q = fmaf(v, v, q);
    }
    atomicAdd(&bnsum[c], s);
    atomicAdd(&bnsq[c], q);
}

// ---------------- batch norm ----------------
__global__ void bn_coef(const float* __restrict__ sum, const float* __restrict__ sq,
                        const float* __restrict__ gamma, const float* __restrict__ beta,
                        float* __restrict__ scale, float* __restrict__ shift) {
    int c = threadIdx.x;
    float mu = sum[c] * (1.f / NN);
    float var = sq[c] * (1.f / NN) - mu * mu;
    float sc = rsqrtf(var + 1e-5f) * gamma[c];
    scale[c] = sc;
    shift[c] = beta[c] - mu * sc;
}

// ---------------- pooling + head ----------------
__global__ void pool_add(const float* __restrict__ x, const int* __restrict__ batch,
                         float* __restrict__ pool) {
    int n = blockIdx.x;
    int c = threadIdx.x;
    atomicAdd(&pool[(size_t)batch[n] * W3 + c], x[(size_t)n * W3 + c]);
}
__global__ void cnt_add(const int* __restrict__ batch, float* __restrict__ cnt) {
    int n = blockIdx.x * blockDim.x + threadIdx.x;
    if (n < NN) atomicAdd(&cnt[batch[n]], 1.f);
}
// mean + layer-3 BN affine folded in (mean(BN(x)) == BN(mean(x)))
__global__ void pool_div_bn(float* __restrict__ pool, const float* __restrict__ cnt,
                            const float* __restrict__ scale, const float* __restrict__ shift) {
    int g = blockIdx.x;
    int c = threadIdx.x;
    float m = pool[(size_t)g * W3 + c] / fmaxf(cnt[g], 1.f);
    pool[(size_t)g * W3 + c] = fmaf(m, scale[c], shift[c]);
}
__global__ void head_kernel(const float* __restrict__ g2, const float* __restrict__ w4,
                            const float* __restrict__ b4, float* __restrict__ out) {
    int g = blockIdx.x * blockDim.x + threadIdx.x;
    if (g >= GG) return;
    float acc[NC];
#pragma unroll
    for (int j = 0; j < NC; j++) acc[j] = b4[j];
    for (int c = 0; c < HID; c++) {
        float v = g2[(size_t)g * HID + c];
#pragma unroll
        for (int j = 0; j < NC; j++) acc[j] = fmaf(v, w4[c * NC + j], acc[j]);
    }
    float mx = acc[0];
#pragma unroll
    for (int j = 1; j < NC; j++) mx = fmaxf(mx, acc[j]);
    float se = 0.f;
#pragma unroll
    for (int j = 0; j < NC; j++) se += expf(acc[j] - mx);
    float l = logf(se) + mx;
#pragma unroll
    for (int j = 0; j < NC; j++) out[(size_t)g * NC + j] = acc[j] - l;
}

extern "C" void kernel_launch(void* const* d_in, const int* in_sizes, int n_in,
                              void* d_out, int out_size) {
    const float* x      = (const float*)d_in[0];
    const int*   ei     = (const int*)d_in[1];
    const int*   batch  = (const int*)d_in[2];
    const float* lin1_w = (const float*)d_in[3];
    const float* lin1_b = (const float*)d_in[4];
    const float* lin2_w = (const float*)d_in[5];
    const float* lin2_b = (const float*)d_in[6];
    const float* w0     = (const float*)d_in[7];
    const float* as0    = (const float*)d_in[8];
    const float* ad0    = (const float*)d_in[9];
    const float* b0     = (const float*)d_in[10];
    const float* wl     = (const float*)d_in[11];
    const float* asl    = (const float*)d_in[12];
    const float* adl    = (const float*)d_in[13];
    const float* bl     = (const float*)d_in[14];
    const float* gamma  = (const float*)d_in[15];
    const float* beta   = (const float*)d_in[16];
    const float* lin3_w = (const float*)d_in[17];
    const float* lin3_b = (const float*)d_in[18];
    const float* lin4_w = (const float*)d_in[19];
    const float* lin4_b = (const float*)d_in[20];
    float* out = (float*)d_out;

    float *pA, *pH, *pes, *ped, *palpha, *ppool, *pcnt, *pg2, *pgb;
    float *pbnsum, *pbnsq, *pscale, *pshift;
    int *pdeg, *poff, *pcur, *pincl, *pbs, *pcsr;
    __nv_bfloat16 *pXhi, *pXlo, *pYhi, *pYlo, *pWhi, *pWlo;
    cudaGetSymbolAddress((void**)&pA, g_bufA);
    cudaGetSymbolAddress((void**)&pH, g_Hf);
    cudaGetSymbolAddress((void**)&pXhi, g_Xhi);
    cudaGetSymbolAddress((void**)&pXlo, g_Xlo);
    cudaGetSymbolAddress((void**)&pYhi, g_Yhi);
    cudaGetSymbolAddress((void**)&pYlo, g_Ylo);
    cudaGetSymbolAddress((void**)&pWhi, g_Whi);
    cudaGetSymbolAddress((void**)&pWlo, g_Wlo);
    cudaGetSymbolAddress((void**)&pes, g_es);
    cudaGetSymbolAddress((void**)&ped, g_ed);
    cudaGetSymbolAddress((void**)&palpha, g_p);
    cudaGetSymbolAddress((void**)&pdeg, g_deg);
    cudaGetSymbolAddress((void**)&poff, g_off);
    cudaGetSymbolAddress((void**)&pcur, g_cur);
    cudaGetSymbolAddress((void**)&pincl, g_incl);
    cudaGetSymbolAddress((void**)&pbs, g_bsum);
    cudaGetSymbolAddress((void**)&pcsr, g_csr);
    cudaGetSymbolAddress((void**)&ppool, g_pool);
    cudaGetSymbolAddress((void**)&pcnt, g_cnt);
    cudaGetSymbolAddress((void**)&pg2, g_g2);
    cudaGetSymbolAddress((void**)&pbnsum, g_bnsum);
    cudaGetSymbolAddress((void**)&pbnsq, g_bnsq);
    cudaGetSymbolAddress((void**)&pscale, g_scale);
    cudaGetSymbolAddress((void**)&pshift, g_shift);
    cudaGetSymbolAddress((void**)&pgb, g_gbias);

    cudaFuncSetAttribute(gemm_mma_kernel<true, false, true, false>,
                         cudaFuncAttributeMaxDynamicSharedMemorySize, SMEM_MMA);
    cudaFuncSetAttribute(gemm_mma_kernel<false, true, false, true>,
                         cudaFuncAttributeMaxDynamicSharedMemorySize, SMEM_MMA);

    const int MB128 = (NN + 127) / 128;   // 782
    const int MB256 = (NN + 255) / 256;   // 391

    // ---- MLP stem ----
    {   // lin1: fp32 gemm, emit bf16 hi/lo directly (relu applied)
        dim3 grid(2, MB128);
        gemm_kernel<true, true><<<grid, 256>>>(x, lin1_w, lin1_b, nullptr,
                                               pXhi, pXlo, NN, F_IN, 2 * HID);
    }
    wsplit<<<(256 * 128 + 255) / 256, 256>>>(lin2_w, pWhi, pWlo, 256, 128);
    {   // lin2: tensor gemm, relu, emit bf16 hi/lo into Y
        dim3 grid(1, MB256);
        gemm_mma_kernel<true, false, true, false><<<grid, 256, SMEM_MMA>>>(
            pXhi, pXlo, pWhi, pWlo, lin2_b, nullptr, pYhi, pYlo,
            nullptr, nullptr, nullptr, nullptr, NN, 256, 128);
    }

    // ---- CSR build (by dst) ----
    zero_i<<<(NN + 255) / 256, 256>>>(pdeg, NN);
    count_deg<<<(ETOT + 255) / 256, 256>>>(ei, pdeg);
    const int NB = (NN + 1023) / 1024;
    scan_block<<<NB, 1024>>>(pdeg, pincl, pbs);
    scan_bsum<<<1, 32>>>(pbs, NB);
    scan_final<<<NB, 1024>>>(pdeg, pincl, pbs, poff, pcur);
    csr_fill<<<(ETOT + 255) / 256, 256>>>(ei, pcur, pcsr);

    // ---- GAT layers (BN of layer l folded into weights/bias of layer l+1) ----
    for (int l = 0; l < 4; l++) {
        const float* W    = (l == 0) ? w0  : wl  + (size_t)(l - 1) * W3 * W3;
        const float* a_s  = (l == 0) ? as0 : asl + (l - 1) * 3 * HID;
        const float* a_d  = (l == 0) ? ad0 : adl + (l - 1) * 3 * HID;
        const float* bias = (l == 0) ? b0  : bl  + (l - 1) * W3;
        const int K       = (l == 0) ? HID : W3;
        const __nv_bfloat16* Ah = (l == 0) ? pYhi : pXhi;
        const __nv_bfloat16* Al = (l == 0) ? pYlo : pXlo;

        const float* gb = nullptr;
        if (l == 0) {
            wsplit<<<(K * W3 + 255) / 256, 256>>>(W, pWhi, pWlo, K, W3);
        } else {
            wsplit_bn<<<(W3 * W3 + 255) / 256, 256>>>(W, pscale, pWhi, pWlo);
            gbias_kernel<<<3, 128>>>(W, pshift, pgb);
            gb = pgb;
        }
        zero_f2<<<(NN * 3 + 255) / 256, 256>>>(pes, ped, NN * 3);
        {
            dim3 grid(3, MB256);
            gemm_mma_kernel<false, true, false, true><<<grid, 256, SMEM_MMA>>>(
                Ah, Al, pWhi, pWlo, gb, pH, nullptr, nullptr,
                a_s, a_d, pes, ped, NN, K, W3);
        }

        attn_csr<<<(NN + 255) / 256, 256>>>(ei, pcsr, poff, pdeg, pes, ped, palpha);

        zero_f2<<<3, 256>>>(pbnsum, pbnsq, W3);
        if (l < 3)
            aggregate<false, true><<<NN / NPB, W3>>>(pH, ei, pcsr, poff, pdeg, palpha, bias,
                                                     nullptr, pXhi, pXlo, pbnsum, pbnsq);
        else
            aggregate<true, false><<<NN / NPB, W3>>>(pH, ei, pcsr, poff, pdeg, palpha, bias,
                                                     pA, nullptr, nullptr, pbnsum, pbnsq);
        bn_coef<<<1, W3>>>(pbnsum, pbnsq, gamma + l * W3, beta + l * W3, pscale, pshift);
    }

    // ---- global mean pool (+ layer-3 BN affine) ----
    zero_f<<<(GG * W3 + 255) / 256, 256>>>(ppool, GG * W3);
    zero_f<<<(GG + 255) / 256, 256>>>(pcnt, GG);
    pool_add<<<NN, W3>>>(pA, batch, ppool);
    cnt_add<<<(NN + 255) / 256, 256>>>(batch, pcnt);
    pool_div_bn<<<GG, W3>>>(ppool, pcnt, pscale, pshift);

    // ---- head ----
    {
        dim3 grid(1, (GG + 127) / 128);
        gemm_kernel<true, false><<<grid, 256>>>(ppool, lin3_w, lin3_b, pg2,
                                                nullptr, nullptr, GG, W3, HID);
    }
    head_kernel<<<(GG + 127) / 128, 128>>>(pg2, lin4_w, lin4_b, out);
}